// round 13
// baseline (speedup 1.0000x reference)
#include <cuda_runtime.h>
#include <cstdint>

// ----------------------------------------------------------------------------
// BaseLUTLayer = multilinear polynomial eval in Moebius coefficient basis.
//   prep_kernel: (a) transpose x -> xT[IN][B] (64x64 float4 tiles)
//                (b) Moebius transform lut -> C
//   lut_fold_kernel: REGISTER-RESIDENT coefficients (c[64] per warp, loaded
//     once), grid split over both o-groups AND batch chunks (1024 blocks).
//     Each loop body processes 64 b as TWO independent 32-lane streams that
//     share the coefficient registers -> doubled ILP to cover x-load latency,
//     with next-body x prefetched. No coefficient memory stream at all.
// ----------------------------------------------------------------------------

#define B_CHUNK 256     // batch elements per block
#define N_BODY  (B_CHUNK / 64)

__device__ float g_xT[4 * 1024 * 1024];
__device__ float g_C [1 * 1024 * 1024];

// ---- fused prep: transpose (first t_blocks) + Moebius coeffs (rest) --------
__global__ __launch_bounds__(256)
void prep_kernel(const float* __restrict__ x, float* __restrict__ xT,
                 const float* __restrict__ lut, float* __restrict__ C,
                 int B, int IN, int OUT, int t_blocks, int tiles_x) {
    if ((int)blockIdx.x < t_blocks) {
        __shared__ float tile[64][65];
        const int tid = threadIdx.x;
        const int c0 = (blockIdx.x % tiles_x) * 64;    // IN base
        const int r0 = (blockIdx.x / tiles_x) * 64;    // B base
        float4 v[4];
#pragma unroll
        for (int p = 0; p < 4; p++) {
            int idx  = p * 256 + tid;
            int row  = idx >> 4;
            int col4 = idx & 15;
            int r = r0 + row, c = c0 + col4 * 4;
            v[p] = (r < B && c + 3 < IN)
                 ? *reinterpret_cast<const float4*>(&x[(size_t)r * IN + c])
                 : make_float4(0.f, 0.f, 0.f, 0.f);
        }
#pragma unroll
        for (int p = 0; p < 4; p++) {
            int idx  = p * 256 + tid;
            int row  = idx >> 4;
            int col4 = idx & 15;
            tile[row][col4 * 4 + 0] = v[p].x;
            tile[row][col4 * 4 + 1] = v[p].y;
            tile[row][col4 * 4 + 2] = v[p].z;
            tile[row][col4 * 4 + 3] = v[p].w;
        }
        __syncthreads();
#pragma unroll
        for (int p = 0; p < 4; p++) {
            int idx = p * 256 + tid;
            int inl = idx >> 4;
            int b4  = idx & 15;
            int in = c0 + inl, bb = r0 + b4 * 4;
            if (in < IN && bb + 3 < B) {
                float4 w = make_float4(tile[b4 * 4 + 0][inl],
                                       tile[b4 * 4 + 1][inl],
                                       tile[b4 * 4 + 2][inl],
                                       tile[b4 * 4 + 3][inl]);
                *reinterpret_cast<float4*>(&xT[(size_t)in * B + bb]) = w;
            }
        }
    } else {
        int o = (blockIdx.x - t_blocks) * 256 + threadIdx.x;
        if (o >= OUT) return;
        float a[64];
        const float4* src = reinterpret_cast<const float4*>(lut + (size_t)o * 64);
#pragma unroll
        for (int i = 0; i < 16; i++) {
            float4 w = __ldg(&src[i]);
            a[4 * i] = w.x; a[4 * i + 1] = w.y; a[4 * i + 2] = w.z; a[4 * i + 3] = w.w;
        }
#pragma unroll
        for (int j = 0; j < 6; j++) {
            int s = 1 << j;
#pragma unroll
            for (int k = 0; k < 64; k++)
                if (k & s) a[k] -= a[k ^ s];
        }
        float4* dst = reinterpret_cast<float4*>(C + (size_t)o * 64);
#pragma unroll
        for (int i = 0; i < 16; i++)
            dst[i] = make_float4(a[4 * i], a[4 * i + 1], a[4 * i + 2], a[4 * i + 3]);
    }
}

// ---- fold: register-resident coeffs, 2-stream bodies, B-split grid ---------
__global__ __launch_bounds__(256, 2)
void lut_fold_kernel(const float* __restrict__ xT,
                     const float* __restrict__ C,
                     const int*   __restrict__ mapping,
                     float* __restrict__ out,
                     int B, int OUT) {
    __shared__ float s_res[8][B_CHUNK + 4];

    const int lane   = threadIdx.x & 31;
    const int w      = threadIdx.x >> 5;          // warp id = o_local
    const int o0     = blockIdx.y * 8;
    const int b_base = blockIdx.x * B_CHUNK;
    int o = o0 + w;
    if (o >= OUT) o = OUT - 1;

    // one-time prologue: coefficients + mapping into registers
    float c[64];
#pragma unroll
    for (int k = 0; k < 64; k++) c[k] = __ldg(&C[(size_t)o * 64 + k]);
    int m[6];
#pragma unroll
    for (int j = 0; j < 6; j++) m[j] = __ldg(&mapping[(size_t)o * 6 + j]);

    // prefetch body 0 (two 32-lane streams)
    float xn[2][6];
#pragma unroll
    for (int s = 0; s < 2; s++) {
        int b = b_base + s * 32 + lane;
#pragma unroll
        for (int j = 0; j < 6; j++)
            xn[s][j] = (b < B) ? __ldg(&xT[(size_t)m[j] * B + b]) : 0.f;
    }

#pragma unroll
    for (int nb = 0; nb < N_BODY; nb++) {
        float xv[2][6];
#pragma unroll
        for (int s = 0; s < 2; s++)
#pragma unroll
            for (int j = 0; j < 6; j++) xv[s][j] = xn[s][j];

        if (nb + 1 < N_BODY) {                    // prefetch next body
#pragma unroll
            for (int s = 0; s < 2; s++) {
                int b = b_base + (nb + 1) * 64 + s * 32 + lane;
#pragma unroll
                for (int j = 0; j < 6; j++)
                    xn[s][j] = (b < B) ? __ldg(&xT[(size_t)m[j] * B + b]) : 0.f;
            }
        }

        // two independent scalar Horner streams sharing c[] registers
#pragma unroll
        for (int s = 0; s < 2; s++) {
            float r[8];
#pragma unroll
            for (int g = 0; g < 8; g++) {
                float v0 = fmaf(xv[s][0], c[8 * g + 1], c[8 * g + 0]);
                float v1 = fmaf(xv[s][0], c[8 * g + 3], c[8 * g + 2]);
                float v2 = fmaf(xv[s][0], c[8 * g + 5], c[8 * g + 4]);
                float v3 = fmaf(xv[s][0], c[8 * g + 7], c[8 * g + 6]);
                float u0 = fmaf(xv[s][1], v1, v0);
                float u1 = fmaf(xv[s][1], v3, v2);
                r[g] = fmaf(xv[s][2], u1, u0);
            }
            float p0 = fmaf(xv[s][3], r[1], r[0]);
            float p1 = fmaf(xv[s][3], r[3], r[2]);
            float p2 = fmaf(xv[s][3], r[5], r[4]);
            float p3 = fmaf(xv[s][3], r[7], r[6]);
            float q0 = fmaf(xv[s][4], p1, p0);
            float q1 = fmaf(xv[s][4], p3, p2);
            float res = fmaf(xv[s][5], q1, q0);

            s_res[w][nb * 64 + s * 32 + lane] = res;   // STS.32 conflict-free
        }
    }
    __syncthreads();

    // writeout: out[b][o0..o0+7] as two float4 (full 32B sectors)
    const int tid = threadIdx.x;
#pragma unroll
    for (int idx = 0; idx < B_CHUNK * 2; idx += 256) {
        int i  = idx + tid;
        int bl = i >> 1;
        int h  = i & 1;
        int b  = b_base + bl;
        int oo = o0 + h * 4;
        if (b < B && oo + 3 < OUT) {
            float4 val = make_float4(s_res[h * 4 + 0][bl],
                                     s_res[h * 4 + 1][bl],
                                     s_res[h * 4 + 2][bl],
                                     s_res[h * 4 + 3][bl]);
            *reinterpret_cast<float4*>(&out[(size_t)b * OUT + oo]) = val;
        }
    }
}

extern "C" void kernel_launch(void* const* d_in, const int* in_sizes, int n_in,
                              void* d_out, int out_size) {
    const float* x       = (const float*)d_in[0];
    const float* lut     = (const float*)d_in[1];
    const int*   mapping = (const int*)d_in[2];
    float*       out     = (float*)d_out;

    int OUT = in_sizes[2] / 6;          // mapping is (OUT, 6)
    int B   = out_size / OUT;           // out is (B, OUT)
    int IN  = in_sizes[0] / B;          // x is (B, IN)

    float* xT = nullptr;
    float* C  = nullptr;
    cudaGetSymbolAddress((void**)&xT, g_xT);
    cudaGetSymbolAddress((void**)&C,  g_C);

    int tiles_x  = (IN + 63) / 64;
    int tiles_y  = (B + 63) / 64;
    int t_blocks = tiles_x * tiles_y;
    int c_blocks = (OUT + 255) / 256;
    prep_kernel<<<t_blocks + c_blocks, 256>>>(x, xT, lut, C, B, IN, OUT, t_blocks, tiles_x);

    dim3 grd((B + B_CHUNK - 1) / B_CHUNK, (OUT + 7) / 8);
    lut_fold_kernel<<<grd, 256>>>(xT, C, mapping, out, B, OUT);
}